// round 10
// baseline (speedup 1.0000x reference)
#include <cuda_runtime.h>
#include <cuda_bf16.h>

// CrossNetwork (DCN-v1), closed form:
//   x_i = c_i * input + d_i
//   d_{i+1} = d_i + b_i ; e_i = d_i.w_i ; S_i = input.w_i (per-row)
//   c_{i+1} = c_i*(1+S_i) + e_i, c_0 = 1 ; out = c_L*input + d_L
//
// R10: R7 structure (proven 30.5us) with register-pressure attack:
//   - prefetch.global.L1 (no dst reg) replaces 16-reg register prefetch
//   - da/db/e moved to smem, loaded pre-barrier (latency hidden by bar)
//   - regs ~126 -> ~95  =>  __launch_bounds__(128,5): 20 warps/SM vs 16
// Batch-2 rows/iter, 20-shfl/row pick6 reduce, 1 barrier/pair unchanged.

#define D    1024
#define D4   (D / 4)
#define L    6
#define TPB  128
#define NW   4

__device__ __forceinline__ void prefetchL1(const void* p) {
    asm volatile("prefetch.global.L1 [%0];" :: "l"(p));
}

__device__ __forceinline__ float pick6(const float a[L], int i) {
    float s = a[0];
    s = (i == 1) ? a[1] : s;
    s = (i == 2) ? a[2] : s;
    s = (i == 3) ? a[3] : s;
    s = (i == 4) ? a[4] : s;
    s = (i == 5) ? a[5] : s;
    return s;
}

__global__ void __launch_bounds__(TPB, 5) cross_fused(const float* __restrict__ input,
                                                      const float* __restrict__ W,
                                                      const float* __restrict__ b,
                                                      float* __restrict__ out,
                                                      int B) {
    const int t = threadIdx.x;
    const int lane = t & 31, warp = t >> 5;
    const unsigned FULL = 0xFFFFFFFFu;

    __shared__ __align__(16) float red[2][L][NW * 2];   // packed partials
    __shared__ __align__(16) float4 sda[TPB], sdb[TPB]; // d_L per-thread slices
    __shared__ __align__(16) float se[8];               // e[0..5] (+pad)

    // ---- W slice for this thread's 8 columns ----
    float4 wa[L], wb[L];
    #pragma unroll
    for (int l = 0; l < L; ++l) {
        wa[l] = __ldg(reinterpret_cast<const float4*>(W + l * D) + 2 * t);
        wb[l] = __ldg(reinterpret_cast<const float4*>(W + l * D) + 2 * t + 1);
    }

    const float4* in4 = reinterpret_cast<const float4*>(input);
    const int grid = gridDim.x;
    const int bid  = blockIdx.x;
    const int totalPairs = B >> 1;          // B even (16384)

    // ---- warm the pipeline: prefetch pairs 0 and 1 for this CTA ----
    {
        int pr = bid;
        if (pr < totalPairs) {
            size_t g = (size_t)(2 * pr) * D4;
            prefetchL1(in4 + g + 2 * t);
            prefetchL1(in4 + g + 2 * t + 1);
            prefetchL1(in4 + g + D4 + 2 * t);
            prefetchL1(in4 + g + D4 + 2 * t + 1);
        }
        pr = bid + grid;
        if (pr < totalPairs) {
            size_t g = (size_t)(2 * pr) * D4;
            prefetchL1(in4 + g + 2 * t);
            prefetchL1(in4 + g + 2 * t + 1);
            prefetchL1(in4 + g + D4 + 2 * t);
            prefetchL1(in4 + g + D4 + 2 * t + 1);
        }
    }

    // ---- per-CTA prologue: d_L and e_l (overlaps prefetch warmup) ----
    {
        float4 da = make_float4(0.f, 0.f, 0.f, 0.f);
        float4 db = make_float4(0.f, 0.f, 0.f, 0.f);
        float pe[L];
        #pragma unroll
        for (int l = 0; l < L; ++l) {
            pe[l] = da.x * wa[l].x + da.y * wa[l].y + da.z * wa[l].z + da.w * wa[l].w
                  + db.x * wb[l].x + db.y * wb[l].y + db.z * wb[l].z + db.w * wb[l].w;
            float4 ba = __ldg(reinterpret_cast<const float4*>(b + l * D) + 2 * t);
            float4 bb = __ldg(reinterpret_cast<const float4*>(b + l * D) + 2 * t + 1);
            da.x += ba.x; da.y += ba.y; da.z += ba.z; da.w += ba.w;
            db.x += bb.x; db.y += bb.y; db.z += bb.z; db.w += bb.w;
        }
        sda[t] = da;
        sdb[t] = db;
        #pragma unroll
        for (int l = 0; l < L; ++l) {
            #pragma unroll
            for (int o = 16; o > 0; o >>= 1) pe[l] += __shfl_xor_sync(FULL, pe[l], o);
            if (lane == 0) red[0][l][warp] = pe[l];
        }
        __syncthreads();
        if (t < L) {
            // every thread could compute e; threads 0..5 publish
            float es[L];
            #pragma unroll
            for (int l = 0; l < L; ++l) {
                float4 q = *reinterpret_cast<const float4*>(&red[0][l][0]);
                es[l] = (q.x + q.y) + (q.z + q.w);
            }
            se[t] = pick6(es, t);
        }
        __syncthreads();   // se/sda/sdb published; red[0] free for reuse
    }

    float4* out4 = reinterpret_cast<float4*>(out);

    int p = 0;
    for (int j = 0; ; ++j, p ^= 1) {
        int pr = bid + j * grid;
        if (pr >= totalPairs) break;

        // ---- load pair j (L1-hot via prefetch at iter j-1) ----
        size_t base = (size_t)(2 * pr) * D4;
        float4 xa0 = in4[base + 2 * t];
        float4 xb0 = in4[base + 2 * t + 1];
        float4 xa1 = in4[base + D4 + 2 * t];
        float4 xb1 = in4[base + D4 + 2 * t + 1];

        // ---- prefetch pair j+2 (zero-register, no scoreboard) ----
        {
            int npr = bid + (j + 2) * grid;
            if (npr < totalPairs) {
                size_t g = (size_t)(2 * npr) * D4;
                prefetchL1(in4 + g + 2 * t);
                prefetchL1(in4 + g + 2 * t + 1);
                prefetchL1(in4 + g + D4 + 2 * t);
                prefetchL1(in4 + g + D4 + 2 * t + 1);
            }
        }

        // ---- dots for both rows ----
        float acc0[L], acc1[L];
        #pragma unroll
        for (int l = 0; l < L; ++l) {
            acc0[l] = xa0.x * wa[l].x + xa0.y * wa[l].y + xa0.z * wa[l].z + xa0.w * wa[l].w
                    + xb0.x * wb[l].x + xb0.y * wb[l].y + xb0.z * wb[l].z + xb0.w * wb[l].w;
            acc1[l] = xa1.x * wa[l].x + xa1.y * wa[l].y + xa1.z * wa[l].z + xa1.w * wa[l].w
                    + xb1.x * wb[l].x + xb1.y * wb[l].y + xb1.z * wb[l].z + xb1.w * wb[l].w;
        }

        // ---- interleaved 3-stage butterflies + pick6 + 2 stages ----
        #pragma unroll
        for (int l = 0; l < L; ++l) {
            acc0[l] += __shfl_xor_sync(FULL, acc0[l], 16);
            acc1[l] += __shfl_xor_sync(FULL, acc1[l], 16);
            acc0[l] += __shfl_xor_sync(FULL, acc0[l], 8);
            acc1[l] += __shfl_xor_sync(FULL, acc1[l], 8);
            acc0[l] += __shfl_xor_sync(FULL, acc0[l], 4);
            acc1[l] += __shfl_xor_sync(FULL, acc1[l], 4);
        }
        float v0 = pick6(acc0, lane >> 2);
        float v1 = pick6(acc1, lane >> 2);
        v0 += __shfl_xor_sync(FULL, v0, 1);
        v1 += __shfl_xor_sync(FULL, v1, 1);
        v0 += __shfl_xor_sync(FULL, v0, 2);
        v1 += __shfl_xor_sync(FULL, v1, 2);
        if (lane < L * 4 && (lane & 3) == 0)
            *reinterpret_cast<float2*>(&red[p][lane >> 2][warp * 2]) = make_float2(v0, v1);

        // ---- read-only constants: issue LDS before bar (latency hidden) ----
        float4 e03 = *reinterpret_cast<const float4*>(&se[0]);
        float2 e45 = *reinterpret_cast<const float2*>(&se[4]);
        float4 da = sda[t];
        float4 db = sdb[t];

        __syncthreads();

        // ---- combine: 2 uniform float4 per layer serve BOTH rows ----
        float c0 = 1.0f, c1 = 1.0f;
        float ee[L] = {e03.x, e03.y, e03.z, e03.w, e45.x, e45.y};
        #pragma unroll
        for (int l = 0; l < L; ++l) {
            float4 q0 = *reinterpret_cast<const float4*>(&red[p][l][0]);
            float4 q1 = *reinterpret_cast<const float4*>(&red[p][l][4]);
            float S0 = (q0.x + q0.z) + (q1.x + q1.z);
            float S1 = (q0.y + q0.w) + (q1.y + q1.w);
            c0 = fmaf(c0, 1.0f + S0, ee[l]);
            c1 = fmaf(c1, 1.0f + S1, ee[l]);
        }

        // ---- epilogue both rows ----
        float4 o0a, o0b, o1a, o1b;
        o0a.x = fmaf(c0, xa0.x, da.x); o0a.y = fmaf(c0, xa0.y, da.y);
        o0a.z = fmaf(c0, xa0.z, da.z); o0a.w = fmaf(c0, xa0.w, da.w);
        o0b.x = fmaf(c0, xb0.x, db.x); o0b.y = fmaf(c0, xb0.y, db.y);
        o0b.z = fmaf(c0, xb0.z, db.z); o0b.w = fmaf(c0, xb0.w, db.w);
        o1a.x = fmaf(c1, xa1.x, da.x); o1a.y = fmaf(c1, xa1.y, da.y);
        o1a.z = fmaf(c1, xa1.z, da.z); o1a.w = fmaf(c1, xa1.w, da.w);
        o1b.x = fmaf(c1, xb1.x, db.x); o1b.y = fmaf(c1, xb1.y, db.y);
        o1b.z = fmaf(c1, xb1.z, db.z); o1b.w = fmaf(c1, xb1.w, db.w);

        out4[base + 2 * t]          = o0a;
        out4[base + 2 * t + 1]      = o0b;
        out4[base + D4 + 2 * t]     = o1a;
        out4[base + D4 + 2 * t + 1] = o1b;
    }
}

extern "C" void kernel_launch(void* const* d_in, const int* in_sizes, int n_in,
                              void* d_out, int out_size) {
    const float* input = (const float*)d_in[0];   // [B, D]
    const float* W     = (const float*)d_in[1];   // [L, D]
    const float* b     = (const float*)d_in[2];   // [L, D]
    float* out = (float*)d_out;

    int B = in_sizes[0] / D;

    int grid = 148 * 5;                 // one wave at 5 CTAs/SM
    int maxg = (B + 1) / 2;
    if (grid > maxg) grid = maxg;

    cross_fused<<<grid, TPB>>>(input, W, b, out, B);
}